// round 2
// baseline (speedup 1.0000x reference)
#include <cuda_runtime.h>
#include <cuda_bf16.h>
#include <cstdint>

#define NRV     40962
#define NHV     163842
#define NR7V    286734
#define M1      81924            // B*NR
#define M2      327684           // B*NH

// ---------------- scratch (device globals; no allocation) ----------------
__device__ __nv_bfloat16 g_x1h[(size_t)M1*128], g_x1l[(size_t)M1*128];
__device__ float         g_h  [(size_t)M1*448];
__device__ __nv_bfloat16 g_xh [(size_t)M2*128], g_xl [(size_t)M2*128];
__device__ float         g_t1 [(size_t)M2*64];
__device__ __nv_bfloat16 g_y1h[(size_t)M2*64],  g_y1l[(size_t)M2*64];
__device__ float         g_t2 [(size_t)M2*64];
__device__ __nv_bfloat16 g_Wuh[128*448], g_Wul[128*448];
__device__ __nv_bfloat16 g_W1h[896*64],  g_W1l[896*64];
__device__ __nv_bfloat16 g_W2h[448*64],  g_W2l[448*64];
__device__ double        g_st[256];
__device__ float         g_sc1[64], g_bb1[64], g_sc2[64], g_bb2[64];

__device__ __forceinline__ void bsplit(float v, __nv_bfloat16& hi, __nv_bfloat16& lo) {
    hi = __float2bfloat16(v);
    lo = __float2bfloat16(v - __bfloat162float(hi));
}

// ---------------- MMA / LDSM helpers ----------------
#define LDSM4(d0,d1,d2,d3,addr) \
    asm volatile("ldmatrix.sync.aligned.m8n8.x4.shared.b16 {%0,%1,%2,%3}, [%4];" \
                 : "=r"(d0),"=r"(d1),"=r"(d2),"=r"(d3) : "r"(addr))
#define LDSM4T(d0,d1,d2,d3,addr) \
    asm volatile("ldmatrix.sync.aligned.m8n8.x4.trans.shared.b16 {%0,%1,%2,%3}, [%4];" \
                 : "=r"(d0),"=r"(d1),"=r"(d2),"=r"(d3) : "r"(addr))
#define MMA_BF16(c,a0,a1,a2,a3,b0,b1) \
    asm volatile("mma.sync.aligned.m16n8k16.row.col.f32.bf16.bf16.f32 " \
                 "{%0,%1,%2,%3}, {%4,%5,%6,%7}, {%8,%9}, {%0,%1,%2,%3};" \
                 : "+f"(c[0]),"+f"(c[1]),"+f"(c[2]),"+f"(c[3]) \
                 : "r"(a0),"r"(a1),"r"(a2),"r"(a3),"r"(b0),"r"(b1))

// ---------------- split-bf16 tensor-core GEMM ----------------
// out[M x Ntot] = gatherA[M x K] @ W[K x Ntot] + bias
// A rows come from (Ah,Al) arrays with SEG channels per source row.
// GATHER: srcRow(seg) = b*NH + neigh[n*7+seg] ; else srcRow = row.
// Block: 256 thr, tile M=128 x N=64. Warp w: rows 16w..16w+15, cols 0..63.
template<int K, int SEG, bool GATHER>
__global__ __launch_bounds__(256, 2)
void mma_gemm(const __nv_bfloat16* __restrict__ Ah, const __nv_bfloat16* __restrict__ Al,
              const __nv_bfloat16* __restrict__ Bh, const __nv_bfloat16* __restrict__ Bl,
              const float* __restrict__ bias, float* __restrict__ out,
              int Mtot, int Ntot, const int* __restrict__ neigh)
{
    // A smem: per term: 128 rows * 80B (two k16 blocks of 32B + 16B pad -> 5*row mod 8 coprime, conflict-free ldmatrix)
    // B smem: per term: 32 rows * 128B, XOR-by-(k&7) 16B-chunk swizzle
    __shared__ __align__(16) uint8_t sA[2 * 128 * 80];
    __shared__ __align__(16) uint8_t sB[2 * 32 * 128];
    const int A_TERM = 128 * 80;
    const int B_TERM = 32 * 128;

    const int tid = threadIdx.x;
    const int rowBase = blockIdx.y * 128;
    const int colBase = blockIdx.x * 64;

    // ---- loader roles ----
    const int arow   = tid & 127;          // A row this thread stages
    const int k16sel = tid >> 7;           // which k16 half of the 32-wide chunk
    const int bkr    = tid >> 3;           // B k-row (0..31)
    const int bnc    = tid & 7;            // B 8-col chunk

    int grA = rowBase + arow;
    int grC = grA < Mtot ? grA : Mtot - 1;
    int bOff = 0, nIdx7 = 0;
    if (GATHER) {
        bOff  = (grC >= NHV) ? NHV : 0;
        nIdx7 = (grC - bOff) * 7;
    }

    uint4 rah0, rah1, ral0, ral1, rbh, rbl;

#define LOAD_REGS(k0_) do { \
        int s_   = (k0_) / SEG; \
        int off_ = (k0_) - s_ * SEG; \
        size_t src_ = GATHER ? (size_t)(bOff + neigh[nIdx7 + s_]) : (size_t)grC; \
        const uint4* pah = (const uint4*)(Ah + src_ * SEG + off_ + k16sel * 16); \
        const uint4* pal = (const uint4*)(Al + src_ * SEG + off_ + k16sel * 16); \
        rah0 = pah[0]; rah1 = pah[1]; ral0 = pal[0]; ral1 = pal[1]; \
        const uint4* pbh = (const uint4*)(Bh + (size_t)((k0_) + bkr) * Ntot + colBase + bnc * 8); \
        const uint4* pbl = (const uint4*)(Bl + (size_t)((k0_) + bkr) * Ntot + colBase + bnc * 8); \
        rbh = *pbh; rbl = *pbl; \
    } while (0)

    // ---- compute roles ----
    const int lane = tid & 31;
    const int w    = tid >> 5;
    const int gid  = lane >> 2;
    const int tig  = lane & 3;
    const int rowA = 16 * w + (lane & 15);
    const int cSel = lane >> 4;           // 0/1: k 0-7 vs 8-15 within k16
    const int krl  = lane & 15;
    const int nHalf = lane >> 4;          // 0/1: n-block halves for B ldmatrix

    uint32_t sAa = (uint32_t)__cvta_generic_to_shared(sA);
    uint32_t sBa = (uint32_t)__cvta_generic_to_shared(sB);
    uint32_t aBase = sAa + rowA * 80 + cSel * 16;

    float acc[8][4];
#pragma unroll
    for (int j = 0; j < 8; j++)
#pragma unroll
        for (int i = 0; i < 4; i++) acc[j][i] = 0.f;

    // STS pointers
    uint4* dstAh = (uint4*)(sA + arow * 80 + k16sel * 32);
    uint4* dstAl = (uint4*)(sA + A_TERM + arow * 80 + k16sel * 32);
    uint4* dstBh = (uint4*)(sB + bkr * 128 + 16 * (bnc ^ (bkr & 7)));
    uint4* dstBl = (uint4*)(sB + B_TERM + bkr * 128 + 16 * (bnc ^ (bkr & 7)));

    LOAD_REGS(0);

#pragma unroll 1
    for (int k0 = 0; k0 < K; k0 += 32) {
        dstAh[0] = rah0; dstAh[1] = rah1;
        dstAl[0] = ral0; dstAl[1] = ral1;
        *dstBh = rbh; *dstBl = rbl;
        __syncthreads();

        if (k0 + 32 < K) LOAD_REGS(k0 + 32);

#pragma unroll
        for (int kk16 = 0; kk16 < 2; kk16++) {
            uint32_t ah0,ah1,ah2,ah3, al0,al1,al2,al3;
            uint32_t aH = aBase + kk16 * 32;
            LDSM4(ah0,ah1,ah2,ah3, aH);
            LDSM4(al0,al1,al2,al3, aH + A_TERM);

            int krow = kk16 * 16 + krl;
            uint32_t bRow = sBa + krow * 128;
            int swzb = krow & 7;
#pragma unroll
            for (int nt = 0; nt < 4; nt++) {
                uint32_t bh0,bh1,bh2,bh3, bl0,bl1,bl2,bl3;
                uint32_t bAddr = bRow + 16 * ((2 * nt + nHalf) ^ swzb);
                LDSM4T(bh0,bh1,bh2,bh3, bAddr);
                LDSM4T(bl0,bl1,bl2,bl3, bAddr + B_TERM);
                MMA_BF16(acc[2*nt],   ah0,ah1,ah2,ah3, bh0,bh1);
                MMA_BF16(acc[2*nt],   ah0,ah1,ah2,ah3, bl0,bl1);
                MMA_BF16(acc[2*nt],   al0,al1,al2,al3, bh0,bh1);
                MMA_BF16(acc[2*nt+1], ah0,ah1,ah2,ah3, bh2,bh3);
                MMA_BF16(acc[2*nt+1], ah0,ah1,ah2,ah3, bl2,bl3);
                MMA_BF16(acc[2*nt+1], al0,al1,al2,al3, bh2,bh3);
            }
        }
        __syncthreads();
    }
#undef LOAD_REGS

    // ---- epilogue ----
    const int r0 = rowBase + 16 * w + gid;
    const int r1 = r0 + 8;
#pragma unroll
    for (int j = 0; j < 8; j++) {
        int cc = colBase + 8 * j + 2 * tig;
        float b0 = bias[cc], b1 = bias[cc + 1];
        if (r0 < Mtot) {
            float2 v = make_float2(acc[j][0] + b0, acc[j][1] + b1);
            *(float2*)(out + (size_t)r0 * Ntot + cc) = v;
        }
        if (r1 < Mtot) {
            float2 v = make_float2(acc[j][2] + b0, acc[j][3] + b1);
            *(float2*)(out + (size_t)r1 * Ntot + cc) = v;
        }
    }
}

// ---------------- auxiliary kernels ----------------
__global__ void split_k(const float* __restrict__ src, __nv_bfloat16* __restrict__ h,
                        __nv_bfloat16* __restrict__ l, int n)
{
    for (int i = blockIdx.x * blockDim.x + threadIdx.x; i < n; i += gridDim.x * blockDim.x) {
        __nv_bfloat16 a, b;
        bsplit(src[i], a, b);
        h[i] = a; l[i] = b;
    }
}

// x = concat(upsample(h), x2) -> split bf16 pair [B, NH, 128]
__global__ void build_x_k(const float* __restrict__ h, const float* __restrict__ x2,
                          const int* __restrict__ topIdx, const int* __restrict__ downIdx,
                          __nv_bfloat16* __restrict__ xh, __nv_bfloat16* __restrict__ xl)
{
    int gr = blockIdx.x;
    int c  = threadIdx.x;           // 0..127
    int b  = (gr >= NHV) ? 1 : 0;
    int n  = gr - b * NHV;
    float v;
    if (c < 64) {
        if (n < NRV) {
            int j = topIdx[n];
            v = h[((size_t)b * NR7V + j) * 64 + c];
        } else {
            int m  = n - NRV;
            int i0 = downIdx[2 * m];
            int i1 = downIdx[2 * m + 1];
            v = 0.5f * (h[((size_t)b * NR7V + i0) * 64 + c] + h[((size_t)b * NR7V + i1) * 64 + c]);
        }
    } else {
        v = x2[(size_t)gr * 64 + (c - 64)];
    }
    __nv_bfloat16 a, bl;
    bsplit(v, a, bl);
    xh[(size_t)gr * 128 + c] = a;
    xl[(size_t)gr * 128 + c] = bl;
}

__global__ void zero_stats_k()
{
    g_st[threadIdx.x] = 0.0;
}

__global__ void stats_k(const float* __restrict__ t, double* __restrict__ st)
{
    int c   = threadIdx.x & 63;
    int sub = threadIdx.x >> 6;
    double s = 0.0, sq = 0.0;
    for (int r = blockIdx.x * 4 + sub; r < M2; r += gridDim.x * 4) {
        float v = t[(size_t)r * 64 + c];
        s  += v;
        sq += (double)v * (double)v;
    }
    __shared__ double sh[512];
    sh[threadIdx.x]       = s;
    sh[256 + threadIdx.x] = sq;
    __syncthreads();
    if (sub == 0) {
#pragma unroll
        for (int i = 1; i < 4; i++) { s += sh[c + 64 * i]; sq += sh[256 + c + 64 * i]; }
        atomicAdd(&st[c], s);
        atomicAdd(&st[64 + c], sq);
    }
}

__global__ void finalize_k(const double* __restrict__ st,
                           const float* __restrict__ gamma, const float* __restrict__ beta,
                           float* __restrict__ sc, float* __restrict__ bb)
{
    int c = threadIdx.x;
    if (c < 64) {
        double inv   = 1.0 / (double)M2;
        double mean  = st[c] * inv;
        double var   = st[64 + c] * inv - mean * mean;
        double scale = (double)gamma[c] / sqrt(var + 1e-5);
        sc[c] = (float)scale;
        bb[c] = (float)((double)beta[c] - mean * scale);
    }
}

// y = split(lrelu(bn(t)))
__global__ void apply_split_k(const float* __restrict__ t, const float* __restrict__ sc,
                              const float* __restrict__ bb,
                              __nv_bfloat16* __restrict__ yh, __nv_bfloat16* __restrict__ yl)
{
    const int total = M2 * 64;
    for (int i = blockIdx.x * blockDim.x + threadIdx.x; i < total; i += gridDim.x * blockDim.x) {
        int c = i & 63;
        float v = t[i] * sc[c] + bb[c];
        v = (v >= 0.f) ? v : 0.2f * v;
        __nv_bfloat16 a, b;
        bsplit(v, a, b);
        yh[i] = a; yl[i] = b;
    }
}

__global__ void apply_out_k(const float* __restrict__ t, const float* __restrict__ sc,
                            const float* __restrict__ bb, float* __restrict__ out)
{
    const int total = M2 * 64;
    for (int i = blockIdx.x * blockDim.x + threadIdx.x; i < total; i += gridDim.x * blockDim.x) {
        int c = i & 63;
        float v = t[i] * sc[c] + bb[c];
        out[i] = (v >= 0.f) ? v : 0.2f * v;
    }
}

// ---------------- launch ----------------
extern "C" void kernel_launch(void* const* d_in, const int* in_sizes, int n_in,
                              void* d_out, int out_size)
{
    const float* x1    = (const float*)d_in[0];
    const float* x2    = (const float*)d_in[1];
    const int*   neigh = (const int*)  d_in[2];
    const int*   topI  = (const int*)  d_in[3];
    const int*   downI = (const int*)  d_in[4];
    const float* upW   = (const float*)d_in[5];
    const float* upB   = (const float*)d_in[6];
    const float* c1W   = (const float*)d_in[7];
    const float* c1b   = (const float*)d_in[8];
    const float* gam1  = (const float*)d_in[9];
    const float* bet1  = (const float*)d_in[10];
    const float* c2W   = (const float*)d_in[11];
    const float* c2b   = (const float*)d_in[12];
    const float* gam2  = (const float*)d_in[13];
    const float* bet2  = (const float*)d_in[14];
    float* out = (float*)d_out;

    __nv_bfloat16 *x1h, *x1l, *xh, *xl, *y1h, *y1l, *Wuh, *Wul, *W1h, *W1l, *W2h, *W2l;
    float *h, *t1, *t2, *sc1, *bb1, *sc2, *bb2;
    double *st;
    cudaGetSymbolAddress((void**)&x1h, g_x1h);  cudaGetSymbolAddress((void**)&x1l, g_x1l);
    cudaGetSymbolAddress((void**)&h,   g_h);
    cudaGetSymbolAddress((void**)&xh,  g_xh);   cudaGetSymbolAddress((void**)&xl,  g_xl);
    cudaGetSymbolAddress((void**)&t1,  g_t1);
    cudaGetSymbolAddress((void**)&y1h, g_y1h);  cudaGetSymbolAddress((void**)&y1l, g_y1l);
    cudaGetSymbolAddress((void**)&t2,  g_t2);
    cudaGetSymbolAddress((void**)&Wuh, g_Wuh);  cudaGetSymbolAddress((void**)&Wul, g_Wul);
    cudaGetSymbolAddress((void**)&W1h, g_W1h);  cudaGetSymbolAddress((void**)&W1l, g_W1l);
    cudaGetSymbolAddress((void**)&W2h, g_W2h);  cudaGetSymbolAddress((void**)&W2l, g_W2l);
    cudaGetSymbolAddress((void**)&st,  g_st);
    cudaGetSymbolAddress((void**)&sc1, g_sc1);  cudaGetSymbolAddress((void**)&bb1, g_bb1);
    cudaGetSymbolAddress((void**)&sc2, g_sc2);  cudaGetSymbolAddress((void**)&bb2, g_bb2);

    zero_stats_k<<<1, 256>>>();

    // precision splits
    split_k<<<4096, 256>>>(x1,  x1h, x1l, M1 * 128);
    split_k<<<112, 256>>>(upW, Wuh, Wul, 128 * 448);
    split_k<<<112, 256>>>(c1W, W1h, W1l, 896 * 64);
    split_k<<<56,  256>>>(c2W, W2h, W2l, 448 * 64);

    // 1) up GEMM: [81924 x 128] @ [128 x 448] + up_b -> h (fp32)
    {
        dim3 grid(7, (M1 + 127) / 128);
        mma_gemm<128, 128, false><<<grid, 256>>>(x1h, x1l, Wuh, Wul, upB, h, M1, 448, nullptr);
    }

    // 2) x = concat(upsample(h), x2) as split bf16
    build_x_k<<<M2, 128>>>(h, x2, topI, downI, xh, xl);

    // 3) conv1: gather(x) [327684 x 896] @ [896 x 64] + b -> t1
    {
        dim3 grid(1, (M2 + 127) / 128);
        mma_gemm<896, 128, true><<<grid, 256>>>(xh, xl, W1h, W1l, c1b, t1, M2, 64, neigh);
    }

    // 4) BN1
    stats_k<<<512, 256>>>(t1, st);
    finalize_k<<<1, 64>>>(st, gam1, bet1, sc1, bb1);
    apply_split_k<<<4096, 256>>>(t1, sc1, bb1, y1h, y1l);

    // 5) conv2: gather(y1) [327684 x 448] @ [448 x 64] + b -> t2
    {
        dim3 grid(1, (M2 + 127) / 128);
        mma_gemm<448, 64, true><<<grid, 256>>>(y1h, y1l, W2h, W2l, c2b, t2, M2, 64, neigh);
    }

    // 6) BN2 + output
    stats_k<<<512, 256>>>(t2, st + 128);
    finalize_k<<<1, 64>>>(st + 128, gam2, bet2, sc2, bb2);
    apply_out_k<<<4096, 256>>>(t2, sc2, bb2, out);
}

// round 4
// speedup vs baseline: 1.0045x; 1.0045x over previous
#include <cuda_runtime.h>
#include <cuda_bf16.h>
#include <cstdint>

#define NRV  40962
#define NHV  163842
#define NR7V 286734
#define M1   81924
#define M2   327684

// ---------------- scratch (device globals) ----------------
__device__ __nv_bfloat16 g_x1h[(size_t)M1*128], g_x1l[(size_t)M1*128];
__device__ unsigned      g_x1p[(size_t)M1*128];
__device__ float         g_h  [(size_t)M1*448];
__device__ __nv_bfloat16 g_xh [(size_t)M2*128], g_xl [(size_t)M2*128];
__device__ unsigned      g_xp [(size_t)M2*128];
__device__ float         g_t1 [(size_t)M2*64];
__device__ __nv_bfloat16 g_y1h[(size_t)M2*64],  g_y1l[(size_t)M2*64];
__device__ unsigned      g_y1p[(size_t)M2*64];
__device__ float         g_t2 [(size_t)M2*64];
__device__ __nv_bfloat16 g_Wuh[128*448], g_Wul[128*448];
__device__ __nv_bfloat16 g_W1h[896*64],  g_W1l[896*64];
__device__ __nv_bfloat16 g_W2h[448*64],  g_W2l[448*64];
__device__ double        g_st[256];
__device__ float         g_sc1[64], g_bb1[64], g_sc2[64], g_bb2[64];

__device__ __forceinline__ void bsplit(float v, __nv_bfloat16& hi, __nv_bfloat16& lo) {
    hi = __float2bfloat16(v);
    lo = __float2bfloat16(v - __bfloat162float(hi));
}
__device__ __forceinline__ unsigned bpack(float v) {
    __nv_bfloat16 a, b; bsplit(v, a, b);
    return (unsigned)__bfloat16_as_ushort(a) | ((unsigned)__bfloat16_as_ushort(b) << 16);
}
__device__ __forceinline__ float bunpack(unsigned p) {
    return __uint_as_float((p & 0xFFFFu) << 16) + __uint_as_float(p & 0xFFFF0000u);
}

// ---------------- MMA / LDSM helpers ----------------
#define LDSM4(d0,d1,d2,d3,addr) \
    asm volatile("ldmatrix.sync.aligned.m8n8.x4.shared.b16 {%0,%1,%2,%3}, [%4];" \
                 : "=r"(d0),"=r"(d1),"=r"(d2),"=r"(d3) : "r"(addr))
#define LDSM4T(d0,d1,d2,d3,addr) \
    asm volatile("ldmatrix.sync.aligned.m8n8.x4.trans.shared.b16 {%0,%1,%2,%3}, [%4];" \
                 : "=r"(d0),"=r"(d1),"=r"(d2),"=r"(d3) : "r"(addr))
#define MMA_BF16(c,a0,a1,a2,a3,b0,b1) \
    asm volatile("mma.sync.aligned.m16n8k16.row.col.f32.bf16.bf16.f32 " \
                 "{%0,%1,%2,%3}, {%4,%5,%6,%7}, {%8,%9}, {%0,%1,%2,%3};" \
                 : "+f"(c[0]),"+f"(c[1]),"+f"(c[2]),"+f"(c[3]) \
                 : "r"(a0),"r"(a1),"r"(a2),"r"(a3),"r"(b0),"r"(b1))

// smem layout (28672 B dynamic):
//  MMA path: A_hi [0,10240) pitch-80, A_lo [10240,20480),
//            B_hi [20480,24576) 32x128B swizzled, B_lo [24576,28672)
//  FFMA path overlay: As float[16][68] at 0 (4352B), Bs float[16][64] at 4352 (4096B)
#define SMEMSZ 28672

// ---------------- hybrid dual-pipe GEMM ----------------
// Tiles interleave: per period of (NMMA+NFF) blocks covering NMMA*128+NFF*64 rows:
//   first NMMA blocks -> 128-row bf16 3-term HMMA tiles
//   next  NFF  blocks -> 64-row fp32 FFMA tiles
template<int K, int SEG, bool GATHER, int NMMA, int NFF>
__global__ void hyb_gemm(const __nv_bfloat16* __restrict__ Ah, const __nv_bfloat16* __restrict__ Al,
                         const unsigned* __restrict__ Apk,
                         const __nv_bfloat16* __restrict__ Bh, const __nv_bfloat16* __restrict__ Bl,
                         const float* __restrict__ Wf,
                         const float* __restrict__ bias, float* __restrict__ out,
                         int Mtot, int Ntot, const int* __restrict__ neigh)
{
    extern __shared__ __align__(1024) uint8_t sm[];
    const int tid = threadIdx.x;
    const int colBase = blockIdx.x * 64;

    const int per = NMMA + NFF;
    const int rpp = NMMA * 128 + NFF * 64;
    const int p   = blockIdx.y / per;
    const int s   = blockIdx.y - p * per;
    const bool isMMA = (s < NMMA);
    const int rowBase = p * rpp + (isMMA ? s * 128 : NMMA * 128 + (s - NMMA) * 64);

    if (isMMA) {
        // ================= HMMA path: 128x64 tile, bf16 3-term =================
        constexpr int NC = K / 32;
        const uint32_t smA = (uint32_t)__cvta_generic_to_shared(sm);

        // loader roles
        const int arow = tid & 127, ahalf = tid >> 7;
        const int gr   = rowBase + arow;
        const int grC  = gr < Mtot ? gr : Mtot - 1;
        int bOff = 0, n7 = 0;
        if (GATHER) { bOff = (grC >= NHV) ? NHV : 0; n7 = (grC - bOff) * 7; }
        const int bk = tid >> 3, bg = tid & 7;
        const uint32_t aS = arow * 80 + ahalf * 32;
        const uint32_t bS = 20480 + bk * 128 + 16 * (bg ^ (bk & 7));

        uint4 rh0, rh1, rl0, rl1, rbh, rbl;
#define LD(c_) do { \
        int seg_, coff_; \
        if (SEG == 128) { seg_ = (c_) >> 2; coff_ = ((c_) & 3) * 32; } \
        else            { seg_ = (c_) >> 1; coff_ = ((c_) & 1) * 32; } \
        size_t src_ = GATHER ? (size_t)(bOff + neigh[n7 + seg_]) : (size_t)grC; \
        const uint4* ph_ = (const uint4*)(Ah + src_ * SEG + coff_ + ahalf * 16); \
        const uint4* pl_ = (const uint4*)(Al + src_ * SEG + coff_ + ahalf * 16); \
        rh0 = ph_[0]; rh1 = ph_[1]; rl0 = pl_[0]; rl1 = pl_[1]; \
        const uint4* pbh_ = (const uint4*)(Bh + (size_t)((c_) * 32 + bk) * Ntot + colBase + bg * 8); \
        const uint4* pbl_ = (const uint4*)(Bl + (size_t)((c_) * 32 + bk) * Ntot + colBase + bg * 8); \
        rbh = *pbh_; rbl = *pbl_; \
    } while (0)

        // compute roles: warp grid 4x2 (wr: 32-row block, wc: 32-col block)
        const int lane = tid & 31, w = tid >> 5;
        const int wr = w & 3, wc = w >> 2;
        const uint32_t aL = smA + (wr * 32 + (lane & 15)) * 80 + (lane >> 4) * 16;
        const int nH   = lane >> 4;
        const int krl  = lane & 15;
        const int swz  = krl & 7;

        float acc[2][4][4];
#pragma unroll
        for (int a = 0; a < 2; a++)
#pragma unroll
            for (int b = 0; b < 4; b++)
#pragma unroll
                for (int q = 0; q < 4; q++) acc[a][b][q] = 0.f;

        LD(0);
#pragma unroll 1
        for (int c = 0; c < NC; c++) {
            *(uint4*)(sm + aS)              = rh0;
            *(uint4*)(sm + aS + 16)         = rh1;
            *(uint4*)(sm + 10240 + aS)      = rl0;
            *(uint4*)(sm + 10240 + aS + 16) = rl1;
            *(uint4*)(sm + bS)              = rbh;
            *(uint4*)(sm + 4096 + bS)       = rbl;
            __syncthreads();
            if (c + 1 < NC) LD(c + 1);

#pragma unroll
            for (int kk = 0; kk < 2; kk++) {
                uint32_t ah[2][4], al[2][4];
#pragma unroll
                for (int mh = 0; mh < 2; mh++) {
                    uint32_t aAddr = aL + mh * (16 * 80) + kk * 32;
                    LDSM4(ah[mh][0], ah[mh][1], ah[mh][2], ah[mh][3], aAddr);
                    LDSM4(al[mh][0], al[mh][1], al[mh][2], al[mh][3], aAddr + 10240);
                }
                const uint32_t bRow = smA + 20480 + (kk * 16 + krl) * 128;
#pragma unroll
                for (int bt = 0; bt < 2; bt++) {
                    const int nt = wc * 2 + bt;
                    uint32_t bh0, bh1, bh2, bh3, bl0, bl1, bl2, bl3;
                    uint32_t bAddr = bRow + 16 * ((2 * nt + nH) ^ swz);
                    LDSM4T(bh0, bh1, bh2, bh3, bAddr);
                    LDSM4T(bl0, bl1, bl2, bl3, bAddr + 4096);
#pragma unroll
                    for (int mh = 0; mh < 2; mh++) {
                        MMA_BF16(acc[mh][2*bt],   ah[mh][0],ah[mh][1],ah[mh][2],ah[mh][3], bh0,bh1);
                        MMA_BF16(acc[mh][2*bt],   ah[mh][0],ah[mh][1],ah[mh][2],ah[mh][3], bl0,bl1);
                        MMA_BF16(acc[mh][2*bt],   al[mh][0],al[mh][1],al[mh][2],al[mh][3], bh0,bh1);
                        MMA_BF16(acc[mh][2*bt+1], ah[mh][0],ah[mh][1],ah[mh][2],ah[mh][3], bh2,bh3);
                        MMA_BF16(acc[mh][2*bt+1], ah[mh][0],ah[mh][1],ah[mh][2],ah[mh][3], bl2,bl3);
                        MMA_BF16(acc[mh][2*bt+1], al[mh][0],al[mh][1],al[mh][2],al[mh][3], bh2,bh3);
                    }
                }
            }
            __syncthreads();
        }
#undef LD
        // epilogue
        const int gid = lane >> 2, tig = lane & 3;
#pragma unroll
        for (int mh = 0; mh < 2; mh++) {
            const int r0 = rowBase + wr * 32 + mh * 16 + gid;
#pragma unroll
            for (int j = 0; j < 4; j++) {
                const int col = colBase + wc * 32 + j * 8 + tig * 2;
                const float b0 = bias[col], b1 = bias[col + 1];
                if (r0 < Mtot)
                    *(float2*)(out + (size_t)r0 * Ntot + col) =
                        make_float2(acc[mh][j][0] + b0, acc[mh][j][1] + b1);
                if (r0 + 8 < Mtot)
                    *(float2*)(out + (size_t)(r0 + 8) * Ntot + col) =
                        make_float2(acc[mh][j][2] + b0, acc[mh][j][3] + b1);
            }
        }
    } else {
        // ================= FFMA path: 64x64 tile, fp32 (hi+lo inputs, fp32 W) =================
        float* As = (float*)sm;            // [16][68]
        float* Bs = (float*)(sm + 4352);   // [16][64]
        const int tx = tid & 15, ty = tid >> 4;

        int src[4]; bool ok[4]; int bB[4], nB[4];
#pragma unroll
        for (int i = 0; i < 4; i++) {
            int gr  = rowBase + ty + 16 * i;
            ok[i]   = (gr < Mtot);
            int grC = ok[i] ? gr : Mtot - 1;
            if (GATHER) { bB[i] = (grC >= NHV) ? NHV : 0; nB[i] = (grC - bB[i]) * 7; }
            src[i] = grC;    // used directly when !GATHER
        }
        float acc[4][4] = {};

#pragma unroll 1
        for (int k0 = 0; k0 < K; k0 += 16) {
            if (GATHER && (k0 % SEG) == 0) {
                int seg = k0 / SEG;
#pragma unroll
                for (int i = 0; i < 4; i++) src[i] = bB[i] + neigh[nB[i] + seg];
            }
#pragma unroll
            for (int i = 0; i < 4; i++) {
                int r = ty + 16 * i;
                float v = 0.f;
                if (ok[i]) v = bunpack(Apk[(size_t)src[i] * SEG + (k0 % SEG) + tx]);
                As[tx * 68 + r] = v;
            }
#pragma unroll
            for (int i = 0; i < 4; i++) {
                int kk = (tid >> 6) + 4 * i;
                int col = tid & 63;
                Bs[kk * 64 + col] = Wf[(size_t)(k0 + kk) * Ntot + colBase + col];
            }
            __syncthreads();
#pragma unroll
            for (int kk = 0; kk < 16; kk++) {
                float4 a4 = *(const float4*)&As[kk * 68 + ty * 4];
                float4 b4 = *(const float4*)&Bs[kk * 64 + tx * 4];
                float av[4] = {a4.x, a4.y, a4.z, a4.w};
                float bv[4] = {b4.x, b4.y, b4.z, b4.w};
#pragma unroll
                for (int i = 0; i < 4; i++)
#pragma unroll
                    for (int j = 0; j < 4; j++) acc[i][j] += av[i] * bv[j];
            }
            __syncthreads();
        }
#pragma unroll
        for (int i = 0; i < 4; i++) {
            int gr = rowBase + ty * 4 + i;
            if (gr >= Mtot) continue;
#pragma unroll
            for (int j = 0; j < 4; j++) {
                int col = colBase + tx * 4 + j;
                out[(size_t)gr * Ntot + col] = acc[i][j] + bias[col];
            }
        }
    }
}

// ---------------- aux kernels ----------------
__global__ void split_x1_k(const float* __restrict__ src)
{
    const int n = M1 * 128;
    for (int i = blockIdx.x * blockDim.x + threadIdx.x; i < n; i += gridDim.x * blockDim.x) {
        float v = src[i];
        __nv_bfloat16 a, b; bsplit(v, a, b);
        g_x1h[i] = a; g_x1l[i] = b;
        g_x1p[i] = (unsigned)__bfloat16_as_ushort(a) | ((unsigned)__bfloat16_as_ushort(b) << 16);
    }
}

__global__ void wprep_k(const float* __restrict__ upW, const float* __restrict__ c1W,
                        const float* __restrict__ c2W)
{
    int i = blockIdx.x * blockDim.x + threadIdx.x;
    for (int t = i; t < 128 * 448; t += gridDim.x * blockDim.x) {
        __nv_bfloat16 a, b; bsplit(upW[t], a, b); g_Wuh[t] = a; g_Wul[t] = b;
    }
    for (int t = i; t < 896 * 64; t += gridDim.x * blockDim.x) {
        __nv_bfloat16 a, b; bsplit(c1W[t], a, b); g_W1h[t] = a; g_W1l[t] = b;
    }
    for (int t = i; t < 448 * 64; t += gridDim.x * blockDim.x) {
        __nv_bfloat16 a, b; bsplit(c2W[t], a, b); g_W2h[t] = a; g_W2l[t] = b;
    }
}

__global__ void build_x_k(const float* __restrict__ h, const float* __restrict__ x2,
                          const int* __restrict__ topIdx, const int* __restrict__ downIdx)
{
    int gr = blockIdx.x;
    int c  = threadIdx.x;
    int b  = (gr >= NHV) ? 1 : 0;
    int n  = gr - b * NHV;
    float v;
    if (c < 64) {
        if (n < NRV) {
            int j = topIdx[n];
            v = h[((size_t)b * NR7V + j) * 64 + c];
        } else {
            int m  = n - NRV;
            int i0 = downIdx[2 * m];
            int i1 = downIdx[2 * m + 1];
            v = 0.5f * (h[((size_t)b * NR7V + i0) * 64 + c] + h[((size_t)b * NR7V + i1) * 64 + c]);
        }
    } else {
        v = x2[(size_t)gr * 64 + (c - 64)];
    }
    __nv_bfloat16 a, bl; bsplit(v, a, bl);
    size_t idx = (size_t)gr * 128 + c;
    g_xh[idx] = a; g_xl[idx] = bl;
    g_xp[idx] = (unsigned)__bfloat16_as_ushort(a) | ((unsigned)__bfloat16_as_ushort(bl) << 16);
}

__global__ void zero_stats_k() { g_st[threadIdx.x] = 0.0; }

__global__ void stats_k(const float* __restrict__ t, double* __restrict__ st)
{
    int c   = threadIdx.x & 63;
    int sub = threadIdx.x >> 6;
    double s = 0.0, sq = 0.0;
    for (int r = blockIdx.x * 4 + sub; r < M2; r += gridDim.x * 4) {
        float v = t[(size_t)r * 64 + c];
        s += v; sq += (double)v * (double)v;
    }
    __shared__ double sh[512];
    sh[threadIdx.x] = s; sh[256 + threadIdx.x] = sq;
    __syncthreads();
    if (sub == 0) {
#pragma unroll
        for (int i = 1; i < 4; i++) { s += sh[c + 64 * i]; sq += sh[256 + c + 64 * i]; }
        atomicAdd(&st[c], s);
        atomicAdd(&st[64 + c], sq);
    }
}

__global__ void finalize_k(const double* __restrict__ st,
                           const float* __restrict__ gamma, const float* __restrict__ beta,
                           float* __restrict__ sc, float* __restrict__ bb)
{
    int c = threadIdx.x;
    if (c < 64) {
        double inv   = 1.0 / (double)M2;
        double mean  = st[c] * inv;
        double var   = st[64 + c] * inv - mean * mean;
        double scale = (double)gamma[c] / sqrt(var + 1e-5);
        sc[c] = (float)scale;
        bb[c] = (float)((double)beta[c] - mean * scale);
    }
}

__global__ void apply_split_k(const float* __restrict__ t, const float* __restrict__ sc,
                              const float* __restrict__ bb)
{
    const int total = M2 * 64;
    for (int i = blockIdx.x * blockDim.x + threadIdx.x; i < total; i += gridDim.x * blockDim.x) {
        int c = i & 63;
        float v = t[i] * sc[c] + bb[c];
        v = (v >= 0.f) ? v : 0.2f * v;
        __nv_bfloat16 a, b; bsplit(v, a, b);
        g_y1h[i] = a; g_y1l[i] = b;
        g_y1p[i] = (unsigned)__bfloat16_as_ushort(a) | ((unsigned)__bfloat16_as_ushort(b) << 16);
    }
}

__global__ void apply_out_k(const float* __restrict__ t, const float* __restrict__ sc,
                            const float* __restrict__ bb, float* __restrict__ out)
{
    const int total = M2 * 64;
    for (int i = blockIdx.x * blockDim.x + threadIdx.x; i < total; i += gridDim.x * blockDim.x) {
        int c = i & 63;
        float v = t[i] * sc[c] + bb[c];
        out[i] = (v >= 0.f) ? v : 0.2f * v;
    }
}

// ---------------- launch ----------------
extern "C" void kernel_launch(void* const* d_in, const int* in_sizes, int n_in,
                              void* d_out, int out_size)
{
    const float* x1    = (const float*)d_in[0];
    const float* x2    = (const float*)d_in[1];
    const int*   neigh = (const int*)  d_in[2];
    const int*   topI  = (const int*)  d_in[3];
    const int*   downI = (const int*)  d_in[4];
    const float* upW   = (const float*)d_in[5];
    const float* upB   = (const float*)d_in[6];
    const float* c1W   = (const float*)d_in[7];
    const float* c1b   = (const float*)d_in[8];
    const float* gam1  = (const float*)d_in[9];
    const float* bet1  = (const float*)d_in[10];
    const float* c2W   = (const float*)d_in[11];
    const float* c2b   = (const float*)d_in[12];
    const float* gam2  = (const float*)d_in[13];
    const float* bet2  = (const float*)d_in[14];
    float* out = (float*)d_out;

    __nv_bfloat16 *x1h, *x1l, *xh, *xl, *y1h, *y1l, *Wuh, *Wul, *W1h, *W1l, *W2h, *W2l;
    unsigned *x1p, *xp, *y1p;
    float *h, *t1, *t2, *sc1, *bb1, *sc2, *bb2;
    double *st;
    cudaGetSymbolAddress((void**)&x1h, g_x1h); cudaGetSymbolAddress((void**)&x1l, g_x1l);
    cudaGetSymbolAddress((void**)&x1p, g_x1p);
    cudaGetSymbolAddress((void**)&h,   g_h);
    cudaGetSymbolAddress((void**)&xh,  g_xh);  cudaGetSymbolAddress((void**)&xl,  g_xl);
    cudaGetSymbolAddress((void**)&xp,  g_xp);
    cudaGetSymbolAddress((void**)&t1,  g_t1);
    cudaGetSymbolAddress((void**)&y1h, g_y1h); cudaGetSymbolAddress((void**)&y1l, g_y1l);
    cudaGetSymbolAddress((void**)&y1p, g_y1p);
    cudaGetSymbolAddress((void**)&t2,  g_t2);
    cudaGetSymbolAddress((void**)&Wuh, g_Wuh); cudaGetSymbolAddress((void**)&Wul, g_Wul);
    cudaGetSymbolAddress((void**)&W1h, g_W1h); cudaGetSymbolAddress((void**)&W1l, g_W1l);
    cudaGetSymbolAddress((void**)&W2h, g_W2h); cudaGetSymbolAddress((void**)&W2l, g_W2l);
    cudaGetSymbolAddress((void**)&st,  g_st);
    cudaGetSymbolAddress((void**)&sc1, g_sc1); cudaGetSymbolAddress((void**)&bb1, g_bb1);
    cudaGetSymbolAddress((void**)&sc2, g_sc2); cudaGetSymbolAddress((void**)&bb2, g_bb2);

    // 1) split x1 into hi/lo/packed
    split_x1_k<<<2048, 256>>>(x1);
    // 2) split weights
    wprep_k<<<448, 256>>>(upW, c1W, c2W);
    // 3) up GEMM (hybrid): [81924 x 128] @ [128 x 448] + up_b -> h
    {
        dim3 grid(7, ((M1 + 255) / 256) * 3);   // period: 1 MMA(128) + 2 FFMA(64)
        hyb_gemm<128, 128, false, 1, 2><<<grid, 256, SMEMSZ>>>(
            x1h, x1l, x1p, Wuh, Wul, upW, upB, h, M1, 448, nullptr);
    }
    // 4) build x
    build_x_k<<<M2, 128>>>(h, x2, topI, downI);
    // 5) zero stats (also positions conv1 as the 6th launch for ncu -s 5)
    zero_stats_k<<<1, 256>>>();
    // 6) conv1 (hybrid): gather [327684 x 896] @ [896 x 64] + b -> t1
    {
        dim3 grid(1, ((M2 + 511) / 512) * 6);   // period: 2 MMA(128) + 4 FFMA(64)
        hyb_gemm<896, 128, true, 2, 4><<<grid, 256, SMEMSZ>>>(
            xh, xl, xp, W1h, W1l, c1W, c1b, t1, M2, 64, neigh);
    }
    // 7-9) BN1 + activation split
    stats_k<<<512, 256>>>(t1, st);
    finalize_k<<<1, 64>>>(st, gam1, bet1, sc1, bb1);
    apply_split_k<<<4096, 256>>>(t1, sc1, bb1);
    // 10) conv2 (hybrid): gather [327684 x 448] @ [448 x 64] + b -> t2
    {
        dim3 grid(1, ((M2 + 511) / 512) * 6);
        hyb_gemm<448, 64, true, 2, 4><<<grid, 256, SMEMSZ>>>(
            y1h, y1l, y1p, W2h, W2l, c2W, c2b, t2, M2, 64, neigh);
    }
    // 11-13) BN2 + output
    stats_k<<<512, 256>>>(t2, st + 128);
    finalize_k<<<1, 64>>>(st + 128, gam2, bet2, sc2, bb2);
    apply_out_k<<<4096, 256>>>(t2, sc2, bb2, out);
}

// round 5
// speedup vs baseline: 1.1011x; 1.0962x over previous
#include <cuda_runtime.h>
#include <cuda_bf16.h>
#include <cstdint>

#define NRV  40962
#define NHV  163842
#define NR7V 286734
#define M1   81924
#define M2   327684

// ---------------- scratch ----------------
__device__ __nv_bfloat16 g_x1h[(size_t)M1*128], g_x1l[(size_t)M1*128];
__device__ float         g_h  [(size_t)M1*448];
__device__ float         g_xf [(size_t)M2*128];
__device__ __nv_bfloat16 g_xh [(size_t)M2*128], g_xl [(size_t)M2*128];
__device__ float         g_t1 [(size_t)M2*64];
__device__ float         g_yf [(size_t)M2*64];
__device__ __nv_bfloat16 g_y1h[(size_t)M2*64],  g_y1l[(size_t)M2*64];
__device__ float         g_t2 [(size_t)M2*64];
__device__ __nv_bfloat16 g_Wuh[128*448], g_Wul[128*448];
__device__ __nv_bfloat16 g_W1h[896*64],  g_W1l[896*64];
__device__ __nv_bfloat16 g_W2h[448*64],  g_W2l[448*64];
__device__ double        g_st[256];
__device__ float         g_sc1[64], g_bb1[64], g_sc2[64], g_bb2[64];

__device__ __forceinline__ void bsplit(float v, __nv_bfloat16& hi, __nv_bfloat16& lo) {
    hi = __float2bfloat16(v);
    lo = __float2bfloat16(v - __bfloat162float(hi));
}
__device__ __forceinline__ unsigned pk2(__nv_bfloat16 a, __nv_bfloat16 b) {
    return (unsigned)__bfloat16_as_ushort(a) | ((unsigned)__bfloat16_as_ushort(b) << 16);
}

// ---------------- MMA / LDSM helpers ----------------
#define LDSM4(d0,d1,d2,d3,addr) \
    asm volatile("ldmatrix.sync.aligned.m8n8.x4.shared.b16 {%0,%1,%2,%3}, [%4];" \
                 : "=r"(d0),"=r"(d1),"=r"(d2),"=r"(d3) : "r"(addr))
#define LDSM4T(d0,d1,d2,d3,addr) \
    asm volatile("ldmatrix.sync.aligned.m8n8.x4.trans.shared.b16 {%0,%1,%2,%3}, [%4];" \
                 : "=r"(d0),"=r"(d1),"=r"(d2),"=r"(d3) : "r"(addr))
#define MMA_BF16(c,a0,a1,a2,a3,b0,b1) \
    asm volatile("mma.sync.aligned.m16n8k16.row.col.f32.bf16.bf16.f32 " \
                 "{%0,%1,%2,%3}, {%4,%5,%6,%7}, {%8,%9}, {%0,%1,%2,%3};" \
                 : "+f"(c[0]),"+f"(c[1]),"+f"(c[2]),"+f"(c[3]) \
                 : "r"(a0),"r"(a1),"r"(a2),"r"(a3),"r"(b0),"r"(b1))
#define BAR_MMA() asm volatile("bar.sync 1, 256;" ::: "memory")
#define BAR_FF()  asm volatile("bar.sync 2, 128;" ::: "memory")

// smem layout (bytes):
//  MMA: A_hi [0,10240) pitch-80, A_lo [10240,20480),
//       B_hi [20480,24576) 32x128B swizzled, B_lo [24576,28672)
//  FF : As fp32 [28672, +8192) = [16][128], Bs fp32 [36864, +4096) = [16][64]
#define FF_A   28672
#define FF_B   36864
#define SMEMSZ 40960

// ---------------- in-CTA dual-pipe GEMM ----------------
// CTA = 384 threads, covers 256 rows x 64 cols:
//   warps 0-7 : rows [0,128)  via 3-term bf16 HMMA
//   warps 8-11: rows [128,256) via fp32 FFMA 8x8 register tiles
template<int K, int SEG, bool GATHER>
__global__ __launch_bounds__(384, 1)
void hyb2_gemm(const __nv_bfloat16* __restrict__ Ah, const __nv_bfloat16* __restrict__ Al,
               const float* __restrict__ Af,
               const __nv_bfloat16* __restrict__ Bh, const __nv_bfloat16* __restrict__ Bl,
               const float* __restrict__ Wf,
               const float* __restrict__ bias, float* __restrict__ out,
               int Mtot, int Ntot, const int* __restrict__ neigh)
{
    extern __shared__ __align__(1024) uint8_t sm[];
    const int tid = threadIdx.x;
    const int colBase = blockIdx.x * 64;
    const int rowCTA  = blockIdx.y * 256;

    if (tid < 256) {
        // ================= HMMA half: rows rowCTA..rowCTA+127 =================
        constexpr int NC = K / 32;
        const uint32_t smA = (uint32_t)__cvta_generic_to_shared(sm);

        const int arow = tid & 127, ahalf = tid >> 7;
        const int gr   = rowCTA + arow;
        const int grC  = gr < Mtot ? gr : Mtot - 1;
        int bOff = 0, n7 = 0;
        if (GATHER) { bOff = (grC >= NHV) ? NHV : 0; n7 = (grC - bOff) * 7; }
        const int bk = tid >> 3, bg = tid & 7;
        const uint32_t aS = arow * 80 + ahalf * 32;
        const uint32_t bS = 20480 + bk * 128 + 16 * (bg ^ (bk & 7));

        uint4 rh0, rh1, rl0, rl1, rbh, rbl;
#define LD(c_) do { \
        int seg_, coff_; \
        if (SEG == 128) { seg_ = (c_) >> 2; coff_ = ((c_) & 3) * 32; } \
        else            { seg_ = (c_) >> 1; coff_ = ((c_) & 1) * 32; } \
        size_t src_ = GATHER ? (size_t)(bOff + neigh[n7 + seg_]) : (size_t)grC; \
        const uint4* ph_ = (const uint4*)(Ah + src_ * SEG + coff_ + ahalf * 16); \
        const uint4* pl_ = (const uint4*)(Al + src_ * SEG + coff_ + ahalf * 16); \
        rh0 = ph_[0]; rh1 = ph_[1]; rl0 = pl_[0]; rl1 = pl_[1]; \
        const uint4* pbh_ = (const uint4*)(Bh + (size_t)((c_) * 32 + bk) * Ntot + colBase + bg * 8); \
        const uint4* pbl_ = (const uint4*)(Bl + (size_t)((c_) * 32 + bk) * Ntot + colBase + bg * 8); \
        rbh = *pbh_; rbl = *pbl_; \
    } while (0)

        const int lane = tid & 31, w = tid >> 5;
        const int wr = w & 3, wc = w >> 2;
        const uint32_t aL = smA + (wr * 32 + (lane & 15)) * 80 + (lane >> 4) * 16;
        const int nH  = lane >> 4;
        const int krl = lane & 15;
        const int swz = krl & 7;

        float acc[2][4][4];
#pragma unroll
        for (int a = 0; a < 2; a++)
#pragma unroll
            for (int b = 0; b < 4; b++)
#pragma unroll
                for (int q = 0; q < 4; q++) acc[a][b][q] = 0.f;

        LD(0);
#pragma unroll 1
        for (int c = 0; c < NC; c++) {
            *(uint4*)(sm + aS)              = rh0;
            *(uint4*)(sm + aS + 16)         = rh1;
            *(uint4*)(sm + 10240 + aS)      = rl0;
            *(uint4*)(sm + 10240 + aS + 16) = rl1;
            *(uint4*)(sm + bS)              = rbh;
            *(uint4*)(sm + 4096 + bS)       = rbl;
            BAR_MMA();
            if (c + 1 < NC) LD(c + 1);

#pragma unroll
            for (int kk = 0; kk < 2; kk++) {
                uint32_t ah[2][4], al[2][4];
#pragma unroll
                for (int mh = 0; mh < 2; mh++) {
                    uint32_t aAddr = aL + mh * (16 * 80) + kk * 32;
                    LDSM4(ah[mh][0], ah[mh][1], ah[mh][2], ah[mh][3], aAddr);
                    LDSM4(al[mh][0], al[mh][1], al[mh][2], al[mh][3], aAddr + 10240);
                }
                const uint32_t bRow = smA + 20480 + (kk * 16 + krl) * 128;
#pragma unroll
                for (int bt = 0; bt < 2; bt++) {
                    const int nt = wc * 2 + bt;
                    uint32_t bh0, bh1, bh2, bh3, bl0, bl1, bl2, bl3;
                    uint32_t bAddr = bRow + 16 * ((2 * nt + nH) ^ swz);
                    LDSM4T(bh0, bh1, bh2, bh3, bAddr);
                    LDSM4T(bl0, bl1, bl2, bl3, bAddr + 4096);
#pragma unroll
                    for (int mh = 0; mh < 2; mh++) {
                        MMA_BF16(acc[mh][2*bt],   ah[mh][0],ah[mh][1],ah[mh][2],ah[mh][3], bh0,bh1);
                        MMA_BF16(acc[mh][2*bt],   ah[mh][0],ah[mh][1],ah[mh][2],ah[mh][3], bl0,bl1);
                        MMA_BF16(acc[mh][2*bt],   al[mh][0],al[mh][1],al[mh][2],al[mh][3], bh0,bh1);
                        MMA_BF16(acc[mh][2*bt+1], ah[mh][0],ah[mh][1],ah[mh][2],ah[mh][3], bh2,bh3);
                        MMA_BF16(acc[mh][2*bt+1], ah[mh][0],ah[mh][1],ah[mh][2],ah[mh][3], bl2,bl3);
                        MMA_BF16(acc[mh][2*bt+1], al[mh][0],al[mh][1],al[mh][2],al[mh][3], bh2,bh3);
                    }
                }
            }
            BAR_MMA();
        }
#undef LD
        const int gid = lane >> 2, tig = lane & 3;
#pragma unroll
        for (int mh = 0; mh < 2; mh++) {
            const int r0 = rowCTA + wr * 32 + mh * 16 + gid;
#pragma unroll
            for (int j = 0; j < 4; j++) {
                const int col = colBase + wc * 32 + j * 8 + tig * 2;
                const float b0 = bias[col], b1 = bias[col + 1];
                if (r0 < Mtot)
                    *(float2*)(out + (size_t)r0 * Ntot + col) =
                        make_float2(acc[mh][j][0] + b0, acc[mh][j][1] + b1);
                if (r0 + 8 < Mtot)
                    *(float2*)(out + (size_t)(r0 + 8) * Ntot + col) =
                        make_float2(acc[mh][j][2] + b0, acc[mh][j][3] + b1);
            }
        }
    } else {
        // ================= FFMA half: rows rowCTA+128 .. +255, 8x8 tiles =================
        float* FAs = (float*)(sm + FF_A);   // [16][128]
        float* FBs = (float*)(sm + FF_B);   // [16][64]
        const int ftid = tid - 256;         // 0..127
        const int frow = rowCTA + 128 + ftid;
        const int frC  = frow < Mtot ? frow : Mtot - 1;
        int fbOff = 0, fn7 = 0;
        if (GATHER) { fbOff = (frC >= NHV) ? NHV : 0; fn7 = (frC - fbOff) * 7; }
        const int tr = ftid >> 3, tc = ftid & 7;
        const int bk2 = ftid >> 3, bc2 = ftid & 7;

        float4 ra[4], rb[2];
#define FLD(k0_) do { \
        int src_ = GATHER ? (fbOff + neigh[fn7 + (k0_) / SEG]) : frC; \
        const float4* pa_ = (const float4*)(Af + (size_t)src_ * SEG + ((k0_) % SEG)); \
        ra[0] = pa_[0]; ra[1] = pa_[1]; ra[2] = pa_[2]; ra[3] = pa_[3]; \
        const float4* pb_ = (const float4*)(Wf + (size_t)((k0_) + bk2) * Ntot + colBase + bc2 * 8); \
        rb[0] = pb_[0]; rb[1] = pb_[1]; \
    } while (0)

        float facc[8][8];
#pragma unroll
        for (int i = 0; i < 8; i++)
#pragma unroll
            for (int j = 0; j < 8; j++) facc[i][j] = 0.f;

        FLD(0);
#pragma unroll 1
        for (int k0 = 0; k0 < K; k0 += 16) {
            if (k0 > 0) BAR_FF();
            const float* rav = (const float*)ra;
#pragma unroll
            for (int i = 0; i < 16; i++) FAs[i * 128 + ftid] = rav[i];
            *(float4*)(FBs + bk2 * 64 + bc2 * 8)     = rb[0];
            *(float4*)(FBs + bk2 * 64 + bc2 * 8 + 4) = rb[1];
            BAR_FF();
            if (k0 + 16 < K) FLD(k0 + 16);
#pragma unroll
            for (int kk = 0; kk < 16; kk++) {
                float4 a0 = *(float4*)(FAs + kk * 128 + tr * 8);
                float4 a1 = *(float4*)(FAs + kk * 128 + tr * 8 + 4);
                float4 b0 = *(float4*)(FBs + kk * 64 + tc * 8);
                float4 b1 = *(float4*)(FBs + kk * 64 + tc * 8 + 4);
                float av[8] = {a0.x,a0.y,a0.z,a0.w,a1.x,a1.y,a1.z,a1.w};
                float bv[8] = {b0.x,b0.y,b0.z,b0.w,b1.x,b1.y,b1.z,b1.w};
#pragma unroll
                for (int i = 0; i < 8; i++)
#pragma unroll
                    for (int j = 0; j < 8; j++) facc[i][j] += av[i] * bv[j];
            }
        }
#undef FLD
#pragma unroll
        for (int i = 0; i < 8; i++) {
            const int r = rowCTA + 128 + tr * 8 + i;
            if (r >= Mtot) continue;
            float* op = out + (size_t)r * Ntot + colBase + tc * 8;
#pragma unroll
            for (int j2 = 0; j2 < 2; j2++) {
                const int cb = colBase + tc * 8 + j2 * 4;
                float4 v;
                v.x = facc[i][j2*4+0] + bias[cb+0];
                v.y = facc[i][j2*4+1] + bias[cb+1];
                v.z = facc[i][j2*4+2] + bias[cb+2];
                v.w = facc[i][j2*4+3] + bias[cb+3];
                *(float4*)(op + j2 * 4) = v;
            }
        }
    }
}

// ---------------- aux kernels ----------------
// prep: zero stats, split x1 and all weights into hi/lo bf16
__global__ void prep_k(const float* __restrict__ x1, const float* __restrict__ upW,
                       const float* __restrict__ c1W, const float* __restrict__ c2W)
{
    int i = blockIdx.x * blockDim.x + threadIdx.x;
    if (i < 256) g_st[i] = 0.0;
    const int stride = gridDim.x * blockDim.x;
    for (int t = i; t < M1 * 128; t += stride) {
        __nv_bfloat16 a, b; bsplit(x1[t], a, b); g_x1h[t] = a; g_x1l[t] = b;
    }
    for (int t = i; t < 128 * 448; t += stride) {
        __nv_bfloat16 a, b; bsplit(upW[t], a, b); g_Wuh[t] = a; g_Wul[t] = b;
    }
    for (int t = i; t < 896 * 64; t += stride) {
        __nv_bfloat16 a, b; bsplit(c1W[t], a, b); g_W1h[t] = a; g_W1l[t] = b;
    }
    for (int t = i; t < 448 * 64; t += stride) {
        __nv_bfloat16 a, b; bsplit(c2W[t], a, b); g_W2h[t] = a; g_W2l[t] = b;
    }
}

// build x = concat(upsample(h), x2): fp32 + bf16 hi/lo. 32 threads per row (4ch each).
__global__ void build_x_k(const float* __restrict__ h, const float* __restrict__ x2,
                          const int* __restrict__ topIdx, const int* __restrict__ downIdx)
{
    int idx = blockIdx.x * 256 + threadIdx.x;
    if (idx >= M2 * 32) return;
    int row = idx >> 5, q = idx & 31;
    int b = (row >= NHV) ? 1 : 0;
    int n = row - b * NHV;
    float4 v;
    if (q < 16) {
        int c = q * 4;
        if (n < NRV) {
            v = *(const float4*)(h + ((size_t)b * NR7V + topIdx[n]) * 64 + c);
        } else {
            int m = n - NRV;
            float4 v0 = *(const float4*)(h + ((size_t)b * NR7V + downIdx[2*m])   * 64 + c);
            float4 v1 = *(const float4*)(h + ((size_t)b * NR7V + downIdx[2*m+1]) * 64 + c);
            v = make_float4(0.5f*(v0.x+v1.x), 0.5f*(v0.y+v1.y), 0.5f*(v0.z+v1.z), 0.5f*(v0.w+v1.w));
        }
    } else {
        v = *(const float4*)(x2 + (size_t)row * 64 + (q - 16) * 4);
    }
    size_t o = (size_t)row * 128 + q * 4;
    *(float4*)(g_xf + o) = v;
    __nv_bfloat16 h0,l0,h1,l1,h2,l2,h3,l3;
    bsplit(v.x,h0,l0); bsplit(v.y,h1,l1); bsplit(v.z,h2,l2); bsplit(v.w,h3,l3);
    *(uint2*)(g_xh + o) = make_uint2(pk2(h0,h1), pk2(h2,h3));
    *(uint2*)(g_xl + o) = make_uint2(pk2(l0,l1), pk2(l2,l3));
}

__global__ void stats_k(const float* __restrict__ t, double* __restrict__ st)
{
    int c   = threadIdx.x & 63;
    int sub = threadIdx.x >> 6;
    double s = 0.0, sq = 0.0;
    for (int r = blockIdx.x * 4 + sub; r < M2; r += gridDim.x * 4) {
        float v = t[(size_t)r * 64 + c];
        s += v; sq += (double)v * (double)v;
    }
    __shared__ double sh[512];
    sh[threadIdx.x] = s; sh[256 + threadIdx.x] = sq;
    __syncthreads();
    if (sub == 0) {
#pragma unroll
        for (int i = 1; i < 4; i++) { s += sh[c + 64 * i]; sq += sh[256 + c + 64 * i]; }
        atomicAdd(&st[c], s);
        atomicAdd(&st[64 + c], sq);
    }
}

__global__ void finalize_k(const double* __restrict__ st,
                           const float* __restrict__ gamma, const float* __restrict__ beta,
                           float* __restrict__ sc, float* __restrict__ bb)
{
    int c = threadIdx.x;
    if (c < 64) {
        double inv   = 1.0 / (double)M2;
        double mean  = st[c] * inv;
        double var   = st[64 + c] * inv - mean * mean;
        double scale = (double)gamma[c] / sqrt(var + 1e-5);
        sc[c] = (float)scale;
        bb[c] = (float)((double)beta[c] - mean * scale);
    }
}

// y = lrelu(bn1(t1)) -> fp32 + hi/lo
__global__ void apply1_k(const float* __restrict__ t, const float* __restrict__ sc,
                         const float* __restrict__ bb)
{
    int i4 = blockIdx.x * blockDim.x + threadIdx.x;
    if (i4 >= M2 * 16) return;
    int c = (i4 & 15) * 4;
    float4 v = *(const float4*)(t + (size_t)i4 * 4);
    v.x = v.x * sc[c+0] + bb[c+0]; v.x = v.x >= 0.f ? v.x : 0.2f * v.x;
    v.y = v.y * sc[c+1] + bb[c+1]; v.y = v.y >= 0.f ? v.y : 0.2f * v.y;
    v.z = v.z * sc[c+2] + bb[c+2]; v.z = v.z >= 0.f ? v.z : 0.2f * v.z;
    v.w = v.w * sc[c+3] + bb[c+3]; v.w = v.w >= 0.f ? v.w : 0.2f * v.w;
    *(float4*)(g_yf + (size_t)i4 * 4) = v;
    __nv_bfloat16 h0,l0,h1,l1,h2,l2,h3,l3;
    bsplit(v.x,h0,l0); bsplit(v.y,h1,l1); bsplit(v.z,h2,l2); bsplit(v.w,h3,l3);
    *(uint2*)(g_y1h + (size_t)i4 * 4) = make_uint2(pk2(h0,h1), pk2(h2,h3));
    *(uint2*)(g_y1l + (size_t)i4 * 4) = make_uint2(pk2(l0,l1), pk2(l2,l3));
}

__global__ void apply_out_k(const float* __restrict__ t, const float* __restrict__ sc,
                            const float* __restrict__ bb, float* __restrict__ out)
{
    int i4 = blockIdx.x * blockDim.x + threadIdx.x;
    if (i4 >= M2 * 16) return;
    int c = (i4 & 15) * 4;
    float4 v = *(const float4*)(t + (size_t)i4 * 4);
    v.x = v.x * sc[c+0] + bb[c+0]; v.x = v.x >= 0.f ? v.x : 0.2f * v.x;
    v.y = v.y * sc[c+1] + bb[c+1]; v.y = v.y >= 0.f ? v.y : 0.2f * v.y;
    v.z = v.z * sc[c+2] + bb[c+2]; v.z = v.z >= 0.f ? v.z : 0.2f * v.z;
    v.w = v.w * sc[c+3] + bb[c+3]; v.w = v.w >= 0.f ? v.w : 0.2f * v.w;
    *(float4*)(out + (size_t)i4 * 4) = v;
}

// ---------------- launch ----------------
extern "C" void kernel_launch(void* const* d_in, const int* in_sizes, int n_in,
                              void* d_out, int out_size)
{
    const float* x1    = (const float*)d_in[0];
    const float* x2    = (const float*)d_in[1];
    const int*   neigh = (const int*)  d_in[2];
    const int*   topI  = (const int*)  d_in[3];
    const int*   downI = (const int*)  d_in[4];
    const float* upW   = (const float*)d_in[5];
    const float* upB   = (const float*)d_in[6];
    const float* c1W   = (const float*)d_in[7];
    const float* c1b   = (const float*)d_in[8];
    const float* gam1  = (const float*)d_in[9];
    const float* bet1  = (const float*)d_in[10];
    const float* c2W   = (const float*)d_in[11];
    const float* c2b   = (const float*)d_in[12];
    const float* gam2  = (const float*)d_in[13];
    const float* bet2  = (const float*)d_in[14];
    float* out = (float*)d_out;

    __nv_bfloat16 *x1h, *x1l, *xh, *xl, *y1h, *y1l, *Wuh, *Wul, *W1h, *W1l, *W2h, *W2l;
    float *h, *xf, *t1, *yf, *t2, *sc1, *bb1, *sc2, *bb2;
    double *st;
    cudaGetSymbolAddress((void**)&x1h, g_x1h); cudaGetSymbolAddress((void**)&x1l, g_x1l);
    cudaGetSymbolAddress((void**)&h,   g_h);
    cudaGetSymbolAddress((void**)&xf,  g_xf);
    cudaGetSymbolAddress((void**)&xh,  g_xh);  cudaGetSymbolAddress((void**)&xl,  g_xl);
    cudaGetSymbolAddress((void**)&t1,  g_t1);
    cudaGetSymbolAddress((void**)&yf,  g_yf);
    cudaGetSymbolAddress((void**)&y1h, g_y1h); cudaGetSymbolAddress((void**)&y1l, g_y1l);
    cudaGetSymbolAddress((void**)&t2,  g_t2);
    cudaGetSymbolAddress((void**)&Wuh, g_Wuh); cudaGetSymbolAddress((void**)&Wul, g_Wul);
    cudaGetSymbolAddress((void**)&W1h, g_W1h); cudaGetSymbolAddress((void**)&W1l, g_W1l);
    cudaGetSymbolAddress((void**)&W2h, g_W2h); cudaGetSymbolAddress((void**)&W2l, g_W2l);
    cudaGetSymbolAddress((void**)&st,  g_st);
    cudaGetSymbolAddress((void**)&sc1, g_sc1); cudaGetSymbolAddress((void**)&bb1, g_bb1);
    cudaGetSymbolAddress((void**)&sc2, g_sc2); cudaGetSymbolAddress((void**)&bb2, g_bb2);

    cudaFuncSetAttribute(hyb2_gemm<128, 128, false>, cudaFuncAttributeMaxDynamicSharedMemorySize, SMEMSZ);
    cudaFuncSetAttribute(hyb2_gemm<896, 128, true>,  cudaFuncAttributeMaxDynamicSharedMemorySize, SMEMSZ);
    cudaFuncSetAttribute(hyb2_gemm<448, 64,  true>,  cudaFuncAttributeMaxDynamicSharedMemorySize, SMEMSZ);

    // 1) prep (splits + zero stats)
    prep_k<<<2048, 256>>>(x1, upW, c1W, c2W);
    // 2) up GEMM: [81924 x 128] @ [128 x 448] + up_b -> h
    {
        dim3 grid(7, (M1 + 255) / 256);
        hyb2_gemm<128, 128, false><<<grid, 384, SMEMSZ>>>(
            x1h, x1l, x1, Wuh, Wul, upW, upB, h, M1, 448, nullptr);
    }
    // 3) build x (fp32 + hi/lo)
    build_x_k<<<(M2 * 32 + 255) / 256, 256>>>(h, x2, topI, downI);
    // 4) conv1: gather [327684 x 896] @ [896 x 64] + b -> t1
    {
        dim3 grid(1, (M2 + 255) / 256);
        hyb2_gemm<896, 128, true><<<grid, 384, SMEMSZ>>>(
            xh, xl, xf, W1h, W1l, c1W, c1b, t1, M2, 64, neigh);
    }
    // 5-7) BN1 + activation
    stats_k<<<512, 256>>>(t1, st);
    finalize_k<<<1, 64>>>(st, gam1, bet1, sc1, bb1);
    apply1_k<<<(M2 * 16 + 255) / 256, 256>>>(t1, sc1, bb1);
    // 8) conv2: gather [327684 x 448] @ [448 x 64] + b -> t2
    {
        dim3 grid(1, (M2 + 255) / 256);
        hyb2_gemm<448, 64, true><<<grid, 384, SMEMSZ>>>(
            y1h, y1l, yf, W2h, W2l, c2W, c2b, t2, M2, 64, neigh);
    }
    // 9-11) BN2 + output
    stats_k<<<512, 256>>>(t2, st + 128);
    finalize_k<<<1, 64>>>(st + 128, gam2, bet2, sc2, bb2);
    apply_out_k<<<(M2 * 16 + 255) / 256, 256>>>(t2, sc2, bb2, out);
}

// round 6
// speedup vs baseline: 2.1193x; 1.9247x over previous
#include <cuda_runtime.h>
#include <cuda_bf16.h>
#include <cstdint>

#define NRV  40962
#define NHV  163842
#define NR7V 286734
#define M1   81924
#define M2   327684

// ---------------- scratch ----------------
__device__ __nv_bfloat16 g_x1h[(size_t)M1*128], g_x1l[(size_t)M1*128];
__device__ float         g_h  [(size_t)M1*448];
__device__ __nv_bfloat16 g_xh [(size_t)M2*128], g_xl [(size_t)M2*128];
__device__ float         g_t1 [(size_t)M2*64];
__device__ __nv_bfloat16 g_y1h[(size_t)M2*64],  g_y1l[(size_t)M2*64];
__device__ float         g_t2 [(size_t)M2*64];
__device__ __nv_bfloat16 g_Wuh[128*448], g_Wul[128*448];
__device__ __nv_bfloat16 g_W1h[896*64],  g_W1l[896*64];
__device__ __nv_bfloat16 g_W2h[448*64],  g_W2l[448*64];
__device__ double        g_st[256];
__device__ float         g_sc1[64], g_bb1[64], g_sc2[64], g_bb2[64];

__device__ __forceinline__ void bsplit(float v, __nv_bfloat16& hi, __nv_bfloat16& lo) {
    hi = __float2bfloat16(v);
    lo = __float2bfloat16(v - __bfloat162float(hi));
}
__device__ __forceinline__ unsigned pk2(__nv_bfloat16 a, __nv_bfloat16 b) {
    return (unsigned)__bfloat16_as_ushort(a) | ((unsigned)__bfloat16_as_ushort(b) << 16);
}

// ---------------- PTX helpers ----------------
#define LDSM4(d0,d1,d2,d3,addr) \
    asm volatile("ldmatrix.sync.aligned.m8n8.x4.shared.b16 {%0,%1,%2,%3}, [%4];" \
                 : "=r"(d0),"=r"(d1),"=r"(d2),"=r"(d3) : "r"(addr))
#define LDSM4T(d0,d1,d2,d3,addr) \
    asm volatile("ldmatrix.sync.aligned.m8n8.x4.trans.shared.b16 {%0,%1,%2,%3}, [%4];" \
                 : "=r"(d0),"=r"(d1),"=r"(d2),"=r"(d3) : "r"(addr))
#define MMA_BF16(c,a0,a1,a2,a3,b0,b1) \
    asm volatile("mma.sync.aligned.m16n8k16.row.col.f32.bf16.bf16.f32 " \
                 "{%0,%1,%2,%3}, {%4,%5,%6,%7}, {%8,%9}, {%0,%1,%2,%3};" \
                 : "+f"(c[0]),"+f"(c[1]),"+f"(c[2]),"+f"(c[3]) \
                 : "r"(a0),"r"(a1),"r"(a2),"r"(a3),"r"(b0),"r"(b1))

__device__ __forceinline__ void cpa16(uint32_t d, const void* s) {
    asm volatile("cp.async.ca.shared.global [%0], [%1], 16;" :: "r"(d), "l"(s) : "memory");
}
#define CP_COMMIT() asm volatile("cp.async.commit_group;" ::: "memory")
#define CP_WAIT1()  asm volatile("cp.async.wait_group 1;" ::: "memory")

// smem per stage (28672 B):
//   A_hi [0,10240) 128 rows pitch 80 (64B data), A_lo [10240,20480)
//   B_hi [20480,24576) 32 rows x 128B XOR-swizzled, B_lo [24576,28672)
#define STG    28672
#define SMEMSZ (2 * STG)

// ---------------- pipelined 3-term bf16 HMMA GEMM ----------------
// out[Mtot x Ntot] = gatherA[Mtot x K] @ W[K x Ntot] + bias
// CTA: 256 thr, tile 128(M) x 64(N); warp (wr,wc) covers 32x32.
template<int K, int SEG, bool GATHER>
__global__ __launch_bounds__(256, 2)
void bf_gemm(const __nv_bfloat16* __restrict__ Ah, const __nv_bfloat16* __restrict__ Al,
             const __nv_bfloat16* __restrict__ Bh, const __nv_bfloat16* __restrict__ Bl,
             const float* __restrict__ bias, float* __restrict__ out,
             int Mtot, int Ntot, const int* __restrict__ neigh)
{
    extern __shared__ __align__(128) uint8_t sm[];
    constexpr int NC = K / 32;
    const uint32_t smA = (uint32_t)__cvta_generic_to_shared(sm);
    const int tid = threadIdx.x;
    const int colBase = blockIdx.x * 64;
    const int rowCTA  = blockIdx.y * 128;

    // ---- loader roles ----
    const int arow = tid >> 1, ahalf = tid & 1;           // A: 2 thr/row, 32B each
    const int gr   = rowCTA + arow;
    const int grC  = gr < Mtot ? gr : Mtot - 1;
    int bOff = 0, n7 = 0;
    if (GATHER) { bOff = (grC >= NHV) ? NHV : 0; n7 = (grC - bOff) * 7; }
    const int bterm = tid >> 7;                           // 0: hi, 1: lo
    const int bk    = (tid & 127) >> 2;                   // B k-row 0..31
    const int bg2   = tid & 3;                            // 2 chunks each
    const __nv_bfloat16* Bsrc = bterm ? Bl : Bh;

    const uint32_t aD  = smA + arow * 80 + ahalf * 32;
    uint32_t bD[2];
#pragma unroll
    for (int j = 0; j < 2; j++) {
        int chunk = bg2 * 2 + j;
        bD[j] = smA + 20480 + bterm * 4096 + bk * 128 + 16 * (chunk ^ (bk & 7));
    }

#define ISSUE(c_) do { \
        const int stage_ = (c_) & 1; \
        const uint32_t so_ = stage_ * STG; \
        int seg_, coff_; \
        if (SEG == 128) { seg_ = (c_) >> 2; coff_ = ((c_) & 3) * 32; } \
        else            { seg_ = (c_) >> 1; coff_ = ((c_) & 1) * 32; } \
        size_t src_ = GATHER ? (size_t)(bOff + neigh[n7 + seg_]) : (size_t)grC; \
        const __nv_bfloat16* pa_ = Ah + src_ * SEG + coff_ + ahalf * 16; \
        cpa16(aD + so_,      pa_); \
        cpa16(aD + so_ + 16, pa_ + 8); \
        const __nv_bfloat16* pl_ = Al + src_ * SEG + coff_ + ahalf * 16; \
        cpa16(aD + so_ + 10240,      pl_); \
        cpa16(aD + so_ + 10240 + 16, pl_ + 8); \
        const __nv_bfloat16* pb_ = Bsrc + (size_t)((c_) * 32 + bk) * Ntot + colBase; \
        cpa16(bD[0] + so_, pb_ + (bg2 * 2 + 0) * 8); \
        cpa16(bD[1] + so_, pb_ + (bg2 * 2 + 1) * 8); \
    } while (0)

    // ---- compute roles ----
    const int lane = tid & 31, w = tid >> 5;
    const int wr = w & 3, wc = w >> 2;
    const uint32_t aL = smA + (wr * 32 + (lane & 15)) * 80 + (lane >> 4) * 16;
    const int nH  = lane >> 4;
    const int krl = lane & 15;
    const int swz = krl & 7;

    float acc[2][4][4];
#pragma unroll
    for (int a = 0; a < 2; a++)
#pragma unroll
        for (int b = 0; b < 4; b++)
#pragma unroll
            for (int q = 0; q < 4; q++) acc[a][b][q] = 0.f;

    // prologue: 2 stages in flight
    ISSUE(0); CP_COMMIT();
    if (NC > 1) ISSUE(1);
    CP_COMMIT();

#pragma unroll 1
    for (int c = 0; c < NC; c++) {
        CP_WAIT1();
        __syncthreads();

        const uint32_t so = (c & 1) * STG;
#pragma unroll
        for (int kk = 0; kk < 2; kk++) {
            uint32_t ah[2][4], al[2][4];
#pragma unroll
            for (int mh = 0; mh < 2; mh++) {
                uint32_t aAddr = aL + so + mh * (16 * 80) + kk * 32;
                LDSM4(ah[mh][0], ah[mh][1], ah[mh][2], ah[mh][3], aAddr);
                LDSM4(al[mh][0], al[mh][1], al[mh][2], al[mh][3], aAddr + 10240);
            }
            const uint32_t bRow = smA + so + 20480 + (kk * 16 + krl) * 128;
#pragma unroll
            for (int bt = 0; bt < 2; bt++) {
                const int nt = wc * 2 + bt;
                uint32_t bh0, bh1, bh2, bh3, bl0, bl1, bl2, bl3;
                uint32_t bAddr = bRow + 16 * ((2 * nt + nH) ^ swz);
                LDSM4T(bh0, bh1, bh2, bh3, bAddr);
                LDSM4T(bl0, bl1, bl2, bl3, bAddr + 4096);
#pragma unroll
                for (int mh = 0; mh < 2; mh++) {
                    MMA_BF16(acc[mh][2*bt],   ah[mh][0],ah[mh][1],ah[mh][2],ah[mh][3], bh0,bh1);
                    MMA_BF16(acc[mh][2*bt],   ah[mh][0],ah[mh][1],ah[mh][2],ah[mh][3], bl0,bl1);
                    MMA_BF16(acc[mh][2*bt],   al[mh][0],al[mh][1],al[mh][2],al[mh][3], bh0,bh1);
                    MMA_BF16(acc[mh][2*bt+1], ah[mh][0],ah[mh][1],ah[mh][2],ah[mh][3], bh2,bh3);
                    MMA_BF16(acc[mh][2*bt+1], ah[mh][0],ah[mh][1],ah[mh][2],ah[mh][3], bl2,bl3);
                    MMA_BF16(acc[mh][2*bt+1], al[mh][0],al[mh][1],al[mh][2],al[mh][3], bh2,bh3);
                }
            }
        }
        __syncthreads();
        if (c + 2 < NC) ISSUE(c + 2);
        CP_COMMIT();   // always commit (possibly empty) to keep group accounting exact
    }
#undef ISSUE

    // ---- epilogue ----
    const int gid = lane >> 2, tig = lane & 3;
#pragma unroll
    for (int mh = 0; mh < 2; mh++) {
        const int r0 = rowCTA + wr * 32 + mh * 16 + gid;
#pragma unroll
        for (int j = 0; j < 4; j++) {
            const int col = colBase + wc * 32 + j * 8 + tig * 2;
            const float b0 = bias[col], b1 = bias[col + 1];
            if (r0 < Mtot)
                *(float2*)(out + (size_t)r0 * Ntot + col) =
                    make_float2(acc[mh][j][0] + b0, acc[mh][j][1] + b1);
            if (r0 + 8 < Mtot)
                *(float2*)(out + (size_t)(r0 + 8) * Ntot + col) =
                    make_float2(acc[mh][j][2] + b0, acc[mh][j][3] + b1);
        }
    }
}

// ---------------- aux kernels ----------------
__global__ void prep_k(const float* __restrict__ x1, const float* __restrict__ upW,
                       const float* __restrict__ c1W, const float* __restrict__ c2W)
{
    int i = blockIdx.x * blockDim.x + threadIdx.x;
    if (i < 256) g_st[i] = 0.0;
    const int stride = gridDim.x * blockDim.x;
    for (int t = i; t < M1 * 128; t += stride) {
        __nv_bfloat16 a, b; bsplit(x1[t], a, b); g_x1h[t] = a; g_x1l[t] = b;
    }
    for (int t = i; t < 128 * 448; t += stride) {
        __nv_bfloat16 a, b; bsplit(upW[t], a, b); g_Wuh[t] = a; g_Wul[t] = b;
    }
    for (int t = i; t < 896 * 64; t += stride) {
        __nv_bfloat16 a, b; bsplit(c1W[t], a, b); g_W1h[t] = a; g_W1l[t] = b;
    }
    for (int t = i; t < 448 * 64; t += stride) {
        __nv_bfloat16 a, b; bsplit(c2W[t], a, b); g_W2h[t] = a; g_W2l[t] = b;
    }
}

__global__ void build_x_k(const float* __restrict__ h, const float* __restrict__ x2,
                          const int* __restrict__ topIdx, const int* __restrict__ downIdx)
{
    int idx = blockIdx.x * 256 + threadIdx.x;
    if (idx >= M2 * 32) return;
    int row = idx >> 5, q = idx & 31;
    int b = (row >= NHV) ? 1 : 0;
    int n = row - b * NHV;
    float4 v;
    if (q < 16) {
        int c = q * 4;
        if (n < NRV) {
            v = *(const float4*)(h + ((size_t)b * NR7V + topIdx[n]) * 64 + c);
        } else {
            int m = n - NRV;
            float4 v0 = *(const float4*)(h + ((size_t)b * NR7V + downIdx[2*m])   * 64 + c);
            float4 v1 = *(const float4*)(h + ((size_t)b * NR7V + downIdx[2*m+1]) * 64 + c);
            v = make_float4(0.5f*(v0.x+v1.x), 0.5f*(v0.y+v1.y), 0.5f*(v0.z+v1.z), 0.5f*(v0.w+v1.w));
        }
    } else {
        v = *(const float4*)(x2 + (size_t)row * 64 + (q - 16) * 4);
    }
    size_t o = (size_t)row * 128 + q * 4;
    __nv_bfloat16 h0,l0,h1,l1,h2,l2,h3,l3;
    bsplit(v.x,h0,l0); bsplit(v.y,h1,l1); bsplit(v.z,h2,l2); bsplit(v.w,h3,l3);
    *(uint2*)(g_xh + o) = make_uint2(pk2(h0,h1), pk2(h2,h3));
    *(uint2*)(g_xl + o) = make_uint2(pk2(l0,l1), pk2(l2,l3));
}

__global__ void stats_k(const float* __restrict__ t, double* __restrict__ st)
{
    int c   = threadIdx.x & 63;
    int sub = threadIdx.x >> 6;
    double s = 0.0, sq = 0.0;
    for (int r = blockIdx.x * 4 + sub; r < M2; r += gridDim.x * 4) {
        float v = t[(size_t)r * 64 + c];
        s += v; sq += (double)v * (double)v;
    }
    __shared__ double sh[512];
    sh[threadIdx.x] = s; sh[256 + threadIdx.x] = sq;
    __syncthreads();
    if (sub == 0) {
#pragma unroll
        for (int i = 1; i < 4; i++) { s += sh[c + 64 * i]; sq += sh[256 + c + 64 * i]; }
        atomicAdd(&st[c], s);
        atomicAdd(&st[64 + c], sq);
    }
}

__global__ void finalize_k(const double* __restrict__ st,
                           const float* __restrict__ gamma, const float* __restrict__ beta,
                           float* __restrict__ sc, float* __restrict__ bb)
{
    int c = threadIdx.x;
    if (c < 64) {
        double inv   = 1.0 / (double)M2;
        double mean  = st[c] * inv;
        double var   = st[64 + c] * inv - mean * mean;
        double scale = (double)gamma[c] / sqrt(var + 1e-5);
        sc[c] = (float)scale;
        bb[c] = (float)((double)beta[c] - mean * scale);
    }
}

__global__ void apply1_k(const float* __restrict__ t, const float* __restrict__ sc,
                         const float* __restrict__ bb)
{
    int i4 = blockIdx.x * blockDim.x + threadIdx.x;
    if (i4 >= M2 * 16) return;
    int c = (i4 & 15) * 4;
    float4 v = *(const float4*)(t + (size_t)i4 * 4);
    v.x = v.x * sc[c+0] + bb[c+0]; v.x = v.x >= 0.f ? v.x : 0.2f * v.x;
    v.y = v.y * sc[c+1] + bb[c+1]; v.y = v.y >= 0.f ? v.y : 0.2f * v.y;
    v.z = v.z * sc[c+2] + bb[c+2]; v.z = v.z >= 0.f ? v.z : 0.2f * v.z;
    v.w = v.w * sc[c+3] + bb[c+3]; v.w = v.w >= 0.f ? v.w : 0.2f * v.w;
    __nv_bfloat16 h0,l0,h1,l1,h2,l2,h3,l3;
    bsplit(v.x,h0,l0); bsplit(v.y,h1,l1); bsplit(v.z,h2,l2); bsplit(v.w,h3,l3);
    *(uint2*)(g_y1h + (size_t)i4 * 4) = make_uint2(pk2(h0,h1), pk2(h2,h3));
    *(uint2*)(g_y1l + (size_t)i4 * 4) = make_uint2(pk2(l0,l1), pk2(l2,l3));
}

__global__ void apply_out_k(const float* __restrict__ t, const float* __restrict__ sc,
                            const float* __restrict__ bb, float* __restrict__ out)
{
    int i4 = blockIdx.x * blockDim.x + threadIdx.x;
    if (i4 >= M2 * 16) return;
    int c = (i4 & 15) * 4;
    float4 v = *(const float4*)(t + (size_t)i4 * 4);
    v.x = v.x * sc[c+0] + bb[c+0]; v.x = v.x >= 0.f ? v.x : 0.2f * v.x;
    v.y = v.y * sc[c+1] + bb[c+1]; v.y = v.y >= 0.f ? v.y : 0.2f * v.y;
    v.z = v.z * sc[c+2] + bb[c+2]; v.z = v.z >= 0.f ? v.z : 0.2f * v.z;
    v.w = v.w * sc[c+3] + bb[c+3]; v.w = v.w >= 0.f ? v.w : 0.2f * v.w;
    *(float4*)(out + (size_t)i4 * 4) = v;
}

// ---------------- launch ----------------
extern "C" void kernel_launch(void* const* d_in, const int* in_sizes, int n_in,
                              void* d_out, int out_size)
{
    const float* x1    = (const float*)d_in[0];
    const float* x2    = (const float*)d_in[1];
    const int*   neigh = (const int*)  d_in[2];
    const int*   topI  = (const int*)  d_in[3];
    const int*   downI = (const int*)  d_in[4];
    const float* upB   = (const float*)d_in[6];
    const float* c1b   = (const float*)d_in[8];
    const float* gam1  = (const float*)d_in[9];
    const float* bet1  = (const float*)d_in[10];
    const float* c2b   = (const float*)d_in[12];
    const float* gam2  = (const float*)d_in[13];
    const float* bet2  = (const float*)d_in[14];
    float* out = (float*)d_out;

    __nv_bfloat16 *x1h, *x1l, *xh, *xl, *y1h, *y1l, *Wuh, *Wul, *W1h, *W1l, *W2h, *W2l;
    float *h, *t1, *t2, *sc1, *bb1, *sc2, *bb2;
    double *st;
    cudaGetSymbolAddress((void**)&x1h, g_x1h); cudaGetSymbolAddress((void**)&x1l, g_x1l);
    cudaGetSymbolAddress((void**)&h,   g_h);
    cudaGetSymbolAddress((void**)&xh,  g_xh);  cudaGetSymbolAddress((void**)&xl,  g_xl);
    cudaGetSymbolAddress((void**)&t1,  g_t1);
    cudaGetSymbolAddress((void**)&y1h, g_y1h); cudaGetSymbolAddress((void**)&y1l, g_y1l);
    cudaGetSymbolAddress((void**)&t2,  g_t2);
    cudaGetSymbolAddress((void**)&Wuh, g_Wuh); cudaGetSymbolAddress((void**)&Wul, g_Wul);
    cudaGetSymbolAddress((void**)&W1h, g_W1h); cudaGetSymbolAddress((void**)&W1l, g_W1l);
    cudaGetSymbolAddress((void**)&W2h, g_W2h); cudaGetSymbolAddress((void**)&W2l, g_W2l);
    cudaGetSymbolAddress((void**)&st,  g_st);
    cudaGetSymbolAddress((void**)&sc1, g_sc1); cudaGetSymbolAddress((void**)&bb1, g_bb1);
    cudaGetSymbolAddress((void**)&sc2, g_sc2); cudaGetSymbolAddress((void**)&bb2, g_bb2);

    cudaFuncSetAttribute(bf_gemm<128, 128, false>, cudaFuncAttributeMaxDynamicSharedMemorySize, SMEMSZ);
    cudaFuncSetAttribute(bf_gemm<896, 128, true>,  cudaFuncAttributeMaxDynamicSharedMemorySize, SMEMSZ);
    cudaFuncSetAttribute(bf_gemm<448, 64,  true>,  cudaFuncAttributeMaxDynamicSharedMemorySize, SMEMSZ);

    // 1) prep
    prep_k<<<2048, 256>>>(x1, (const float*)d_in[5], (const float*)d_in[7], (const float*)d_in[11]);
    // 2) up GEMM
    {
        dim3 grid(7, (M1 + 127) / 128);
        bf_gemm<128, 128, false><<<grid, 256, SMEMSZ>>>(x1h, x1l, Wuh, Wul, upB, h, M1, 448, nullptr);
    }
    // 3) build x
    build_x_k<<<(M2 * 32 + 255) / 256, 256>>>(h, x2, topI, downI);
    // 4) conv1
    {
        dim3 grid(1, (M2 + 127) / 128);
        bf_gemm<896, 128, true><<<grid, 256, SMEMSZ>>>(xh, xl, W1h, W1l, c1b, t1, M2, 64, neigh);
    }
    // 5-7) BN1 + activation
    stats_k<<<512, 256>>>(t1, st);
    finalize_k<<<1, 64>>>(st, gam1, bet1, sc1, bb1);
    apply1_k<<<(M2 * 16 + 255) / 256, 256>>>(t1, sc1, bb1);
    // 8) conv2
    {
        dim3 grid(1, (M2 + 127) / 128);
        bf_gemm<448, 64, true><<<grid, 256, SMEMSZ>>>(y1h, y1l, W2h, W2l, c2b, t2, M2, 64, neigh);
    }
    // 9-11) BN2 + output
    stats_k<<<512, 256>>>(t2, st + 128);
    finalize_k<<<1, 64>>>(st + 128, gam2, bet2, sc2, bb2);
    apply_out_k<<<(M2 * 16 + 255) / 256, 256>>>(t2, sc2, bb2, out);
}